// round 9
// baseline (speedup 1.0000x reference)
#include <cuda_runtime.h>
#include <cuda_bf16.h>
#include <cstdint>

// Problem constants
#define N_MLP        64
#define N_GRID_PTS   16384            // 128*128
#define FLOATS_PER_M (N_GRID_PTS * 3) // 49152
// W row-major [64][1026][3]; per-m dot region = 3072 contiguous floats at m*3078.

// Per-MLP params: [b0,b1,b2, wx0,wx1,wx2, wy0,wy1,wy2, dx0,dx1,dx2, pad]
__device__ float g_p[N_MLP * 16];

// HW tanh (MUFU.TANH). Max rel err ~2^-11, well under the 1e-3 gate.
__device__ __forceinline__ float htanh(float v) {
    float r;
    asm("tanh.approx.f32 %0, %1;" : "=f"(r) : "f"(v));
    return r;
}

// ---------------------------------------------------------------------------
// Kernel 1: per-MLP parameter precompute. 64 blocks x 512 threads.
// Each thread dots 6 consecutive W floats (= points 2t, 2t+1 across o) with
// x[2t..2t+1]. Triggers PDL completion at entry.
// ---------------------------------------------------------------------------
__global__ void __launch_bounds__(512)
precompute_kernel(const float* __restrict__ x,
                  const float* __restrict__ W,
                  const float* __restrict__ b) {
    cudaTriggerProgrammaticLaunchCompletion();

    __shared__ float sW[3072];
    __shared__ float sh[16][3];

    const int tid = threadIdx.x;
    const int m   = blockIdx.x;
    const float* __restrict__ Wm = W + (size_t)m * 3078;

    // stage W dot-region coalesced (8B-aligned for all m): 3 float2/thread
    const float2* __restrict__ W2 = (const float2*)Wm;
    float2* sW2 = (float2*)sW;
    #pragma unroll
    for (int k = 0; k < 3; k++)
        sW2[k * 512 + tid] = W2[k * 512 + tid];
    __syncthreads();

    // dot: x[2t..2t+1] against smem floats [6t..6t+5]
    const float2 xv = ((const float2*)x)[tid];
    const float2* f2 = (const float2*)(sW + 6 * tid);
    const float2 a = f2[0], c = f2[1], d = f2[2];

    float s0 = xv.x * a.x,            s1 = xv.x * a.y,            s2 = xv.x * c.x;
    s0 = fmaf(xv.y, c.y, s0); s1 = fmaf(xv.y, d.x, s1); s2 = fmaf(xv.y, d.y, s2);

    #pragma unroll
    for (int off = 16; off; off >>= 1) {
        s0 += __shfl_xor_sync(0xffffffffu, s0, off);
        s1 += __shfl_xor_sync(0xffffffffu, s1, off);
        s2 += __shfl_xor_sync(0xffffffffu, s2, off);
    }
    const int w = tid >> 5, l = tid & 31;
    if (l == 0) { sh[w][0] = s0; sh[w][1] = s1; sh[w][2] = s2; }
    __syncthreads();

    const float inv127 = 1.0f / 127.0f;
    float* pm = g_p + m * 16;
    if (tid < 3) {                          // base
        float acc = b[m * 3 + tid];
        #pragma unroll
        for (int ww = 0; ww < 16; ww++) acc += sh[ww][tid];
        pm[tid] = acc;
    } else if (tid < 6) {                   // wx + dx
        const float wx = Wm[3072 + (tid - 3)];
        pm[tid]     = wx;
        pm[tid + 6] = wx * inv127;          // dx at 9..11
    } else if (tid < 9) {                   // wy
        pm[tid] = Wm[3072 + (tid - 3)];
    } else if (tid < 13) {
        pm[tid + 3] = 0.0f;                 // pad 12..15
    }
}

// ---------------------------------------------------------------------------
// Kernel 2: decode, warp-per-row. 1024 blocks x 256 threads (one wave).
// Global row R = blk*8 + warp; m = R>>7 (uniform per block), gy = (R&127)/127.
// Warp covers the row's 384 output floats with 3 coalesced 512B stores.
// Per lane: Floc(s) = 128s + 4l; g = Floc/3 in [0,127] IS the x-index (no 2D
// decode, no row wrap). ay = b + gy*wy hoisted per warp. V0..V2 = point g,
// V3..V5 = V + dx (point g+1), elements e_j = V[cs+j] via SELs, tanh, STG.128.
// ---------------------------------------------------------------------------
__global__ void __launch_bounds__(256)
decode_kernel(float* __restrict__ out) {
    const int tid = threadIdx.x;
    const int w   = tid >> 5, l = tid & 31;
    const int R   = blockIdx.x * 8 + w;        // global row
    const int m   = R >> 7;

    // param-independent setup (overlaps precompute under PDL)
    const float inv127 = 1.0f / 127.0f;
    const float gy = (float)(R & 127) * inv127;
    float* __restrict__ outr = out + (size_t)R * 384 + (l << 2);
    int g  = (int)(((unsigned)(l << 2) * 43691u) >> 17);   // (4l)/3
    int cs = (l << 2) - 3 * g;                             // (4l)%3

    cudaGridDependencySynchronize();

    const float4* __restrict__ P = (const float4*)(g_p + m * 16);
    const float4 A = P[0], B = P[1], C = P[2];
    const float b0 = A.x, b1 = A.y, b2 = A.z;
    const float wx0 = A.w, wx1 = B.x, wx2 = B.y;
    const float wy0 = B.z, wy1 = B.w, wy2 = C.x;
    const float dx0 = C.y, dx1 = C.z, dx2 = C.w;

    // hoist the row term
    const float ay0 = fmaf(gy, wy0, b0);
    const float ay1 = fmaf(gy, wy1, b1);
    const float ay2 = fmaf(gy, wy2, b2);

    #pragma unroll
    for (int s = 0; s < 3; s++) {
        const float gx = (float)g * inv127;

        const float V0 = fmaf(gx, wx0, ay0);
        const float V1 = fmaf(gx, wx1, ay1);
        const float V2 = fmaf(gx, wx2, ay2);
        const float V3 = V0 + dx0;            // point g+1 (g+1 <= 127 always)
        const float V4 = V1 + dx1;
        const float V5 = V2 + dx2;

        const bool c1 = (cs == 1), c2 = (cs == 2);
        const float e0 = c2 ? V2 : (c1 ? V1 : V0);
        const float e1 = c2 ? V3 : (c1 ? V2 : V1);
        const float e2 = c2 ? V4 : (c1 ? V3 : V2);
        const float e3 = c2 ? V5 : (c1 ? V4 : V3);

        *(float4*)(outr + (s << 7)) =
            make_float4(htanh(e0), htanh(e1), htanh(e2), htanh(e3));

        // Floc += 128  =>  g += 42, cs += 2 (carry -> g += 1)
        g += 42; cs += 2;
        if (cs >= 3) { cs -= 3; g += 1; }
    }
}

// Inputs (metadata order): x[1024] f32, W[64*1026*3] f32, b[64*3] f32,
//                          grid[16384*2] f32 (unused).  Output: f32[64*16384*3].
extern "C" void kernel_launch(void* const* d_in, const int* in_sizes, int n_in,
                              void* d_out, int out_size) {
    const float* x = (const float*)d_in[0];
    const float* W = (const float*)d_in[1];
    const float* b = (const float*)d_in[2];
    float* out     = (float*)d_out;

    precompute_kernel<<<N_MLP, 512>>>(x, W, b);

    // decode with programmatic dependent launch: overlap launch ramp + setup
    // with precompute execution; device-side sync gates the g_p read.
    cudaLaunchConfig_t cfg = {};
    cfg.gridDim  = dim3(1024, 1, 1);
    cfg.blockDim = dim3(256, 1, 1);
    cfg.dynamicSmemBytes = 0;
    cudaLaunchAttribute attr[1];
    attr[0].id = cudaLaunchAttributeProgrammaticStreamSerialization;
    attr[0].val.programmaticStreamSerializationAllowed = 1;
    cfg.attrs = attr;
    cfg.numAttrs = 1;
    cudaLaunchKernelEx(&cfg, decode_kernel, out);
}